// round 7
// baseline (speedup 1.0000x reference)
#include <cuda_runtime.h>
#include <math.h>

// Problem constants (fixed by reference setup_inputs)
#define B  4
#define T  4096
#define C  64
#define HS 64
#define BT (B * T)

// Scratch for q, k, v projections (device globals; no allocations allowed)
__device__ float g_q[BT * HS];
__device__ float g_k[BT * HS];
__device__ float g_v[BT * HS];

// Streams with priorities + fork/join events, created once at init.
static cudaStream_t g_sZero;   // low priority  : bulk zero-fill
static cudaStream_t g_sComp;   // high priority : qkv -> band
static cudaEvent_t  g_evFork, g_evZ, g_evC;
namespace {
struct InitStreams {
    InitStreams() {
        int leastPrio = 0, greatestPrio = 0;
        cudaDeviceGetStreamPriorityRange(&leastPrio, &greatestPrio);
        cudaStreamCreateWithPriority(&g_sZero, cudaStreamNonBlocking, leastPrio);
        cudaStreamCreateWithPriority(&g_sComp, cudaStreamNonBlocking, greatestPrio);
        cudaEventCreateWithFlags(&g_evFork, cudaEventDisableTiming);
        cudaEventCreateWithFlags(&g_evZ, cudaEventDisableTiming);
        cudaEventCreateWithFlags(&g_evC, cudaEventDisableTiming);
    }
};
InitStreams g_initStreams;
}

// ---------------------------------------------------------------------------
// Kernel Z: zero-fill rows [row0, row0 + nblocks*8) of attn, skipping the <=2
// band float4 slots per row (band_kernel writes those at disjoint addresses).
// One warp per (b, t) row. 0 smem, 16 regs -> backfills any free warp slot.
// ---------------------------------------------------------------------------
__global__ __launch_bounds__(256, 8)
void zero_kernel(float* __restrict__ attn_out,   // [B, T, T]
                 int row0)
{
    const int warp_in_blk = threadIdx.x >> 5;
    const int lane = threadIdx.x & 31;
    const int w = row0 + blockIdx.x * 8 + warp_in_blk;   // row id in [0, BT)
    const int b = w >> 12;
    const int t = w & (T - 1);

    const int lo = max(t - 2, 0);
    const int hi = min(t + 2, T - 1);
    const int fa = lo >> 2;
    const int fb = hi >> 2;

    float4* row4 = reinterpret_cast<float4*>(
        attn_out + (size_t)b * T * T + (size_t)t * T);
    const float4 z = make_float4(0.f, 0.f, 0.f, 0.f);

    #pragma unroll 4
    for (int i4 = lane; i4 < T / 4; i4 += 32) {
        if (i4 != fa && i4 != fb) __stcs(&row4[i4], z);
    }
}

// ---------------------------------------------------------------------------
// Kernel 1: QKV projection.  out[t][h] = sum_c x[t][c] * W[h][c]
// Grid: (BT/64, 3). Block: 256 threads. Tile: 64x64, 4x4 per thread.
// Smem strides padded to 68 floats (16B-aligned) so the inner loop runs on
// LDS.128 (2 per c-iter) instead of 8 scalar LDS.
// ---------------------------------------------------------------------------
#define QSTR 68
__global__ __launch_bounds__(256, 4)
void qkv_kernel(const float* __restrict__ x,
                const float* __restrict__ Wq,
                const float* __restrict__ Wk,
                const float* __restrict__ Wv)
{
    __shared__ float xs[64 * QSTR];   // xs[c][m] = x[row0+m][c]
    __shared__ float ws[64 * QSTR];   // ws[c][h] = W[h][c]

    const float* W;
    float* out;
    if (blockIdx.y == 0)      { W = Wq; out = g_q; }
    else if (blockIdx.y == 1) { W = Wk; out = g_k; }
    else                      { W = Wv; out = g_v; }

    const int row0 = blockIdx.x * 64;
    const int tid = threadIdx.x;

    #pragma unroll
    for (int idx = tid; idx < 64 * 64; idx += 256) {
        int h = idx >> 6, c = idx & 63;
        ws[c * QSTR + h] = W[idx];
    }
    #pragma unroll
    for (int idx = tid; idx < 64 * 64; idx += 256) {
        int m = idx >> 6, c = idx & 63;
        xs[c * QSTR + m] = x[(size_t)(row0 + m) * C + c];
    }
    __syncthreads();

    const int tm = (tid >> 4) * 4;   // 16B-aligned row group
    const int tn = (tid & 15) * 4;   // 16B-aligned col group

    float acc[4][4];
    #pragma unroll
    for (int i = 0; i < 4; i++)
        #pragma unroll
        for (int j = 0; j < 4; j++) acc[i][j] = 0.0f;

    const float4* xs4 = reinterpret_cast<const float4*>(&xs[tm]);
    const float4* ws4 = reinterpret_cast<const float4*>(&ws[tn]);

    #pragma unroll 8
    for (int c = 0; c < 64; ++c) {
        const float4 a4 = xs4[c * (QSTR / 4)];
        const float4 b4 = ws4[c * (QSTR / 4)];
        acc[0][0] += a4.x * b4.x; acc[0][1] += a4.x * b4.y;
        acc[0][2] += a4.x * b4.z; acc[0][3] += a4.x * b4.w;
        acc[1][0] += a4.y * b4.x; acc[1][1] += a4.y * b4.y;
        acc[1][2] += a4.y * b4.z; acc[1][3] += a4.y * b4.w;
        acc[2][0] += a4.z * b4.x; acc[2][1] += a4.z * b4.y;
        acc[2][2] += a4.z * b4.z; acc[2][3] += a4.z * b4.w;
        acc[3][0] += a4.w * b4.x; acc[3][1] += a4.w * b4.y;
        acc[3][2] += a4.w * b4.z; acc[3][3] += a4.w * b4.w;
    }

    #pragma unroll
    for (int i = 0; i < 4; i++) {
        float4 v4 = make_float4(acc[i][0], acc[i][1], acc[i][2], acc[i][3]);
        *reinterpret_cast<float4*>(&out[(size_t)(row0 + tm + i) * HS + tn]) = v4;
    }
}

// ---------------------------------------------------------------------------
// Kernel 2: band attention. One warp per (b, t) row: 5 dots, softmax, op row,
// and ONLY the <=2 band float4 slots of the attn row (zeros done elsewhere at
// disjoint addresses, no ordering needed).
// ---------------------------------------------------------------------------
__global__ __launch_bounds__(256, 8)
void band_kernel(float* __restrict__ op_out,    // [B*T, 64]
                 float* __restrict__ attn_out)  // [B, T, T]
{
    const int warp_in_blk = threadIdx.x >> 5;
    const int lane = threadIdx.x & 31;
    const int w = blockIdx.x * 8 + warp_in_blk;
    const int b = w >> 12;
    const int t = w & (T - 1);

    const float2 myq = reinterpret_cast<const float2*>(g_q + (size_t)w * HS)[lane];

    float score[5];
    #pragma unroll
    for (int d = 0; d < 5; ++d) {
        const int s = t - 2 + d;
        const bool valid = (unsigned)s < (unsigned)T;
        float p = 0.0f;
        if (valid) {
            const float2 kk =
                reinterpret_cast<const float2*>(g_k + ((size_t)(b * T + s)) * HS)[lane];
            p = myq.x * kk.x + myq.y * kk.y;
        }
        #pragma unroll
        for (int off = 16; off > 0; off >>= 1)
            p += __shfl_xor_sync(0xFFFFFFFFu, p, off);
        // scale = C^-0.5 = 1/8 ; triu quirk: +1.0 when s > t (d > 2)
        score[d] = valid ? (p * 0.125f + (d > 2 ? 1.0f : 0.0f)) : -1e30f;
    }

    float m = score[0];
    #pragma unroll
    for (int d = 1; d < 5; ++d) m = fmaxf(m, score[d]);
    float p5[5], sum = 0.0f;
    #pragma unroll
    for (int d = 0; d < 5; ++d) { p5[d] = expf(score[d] - m); sum += p5[d]; }
    const float inv = 1.0f / sum;
    #pragma unroll
    for (int d = 0; d < 5; ++d) p5[d] *= inv;

    // op row: each lane owns 2 channels
    float2 acc = make_float2(0.0f, 0.0f);
    #pragma unroll
    for (int d = 0; d < 5; ++d) {
        const int s = t - 2 + d;
        if ((unsigned)s < (unsigned)T) {
            const float2 vv =
                reinterpret_cast<const float2*>(g_v + ((size_t)(b * T + s)) * HS)[lane];
            acc.x += p5[d] * vv.x;
            acc.y += p5[d] * vv.y;
        }
    }
    reinterpret_cast<float2*>(op_out + (size_t)w * HS)[lane] = acc;

    // band float4 slots
    const int lo = max(t - 2, 0);
    const int hi = min(t + 2, T - 1);
    const int fa = lo >> 2;
    const int fb = hi >> 2;

    #define BV(s_) (((s_) >= lo && (s_) <= hi)                                   \
                      ? ((s_) == t - 2 ? p5[0]                                   \
                       : (s_) == t - 1 ? p5[1]                                   \
                       : (s_) == t     ? p5[2]                                   \
                       : (s_) == t + 1 ? p5[3] : p5[4])                          \
                      : 0.0f)
    const float4 va = make_float4(BV(4 * fa + 0), BV(4 * fa + 1),
                                  BV(4 * fa + 2), BV(4 * fa + 3));
    const float4 vb = make_float4(BV(4 * fb + 0), BV(4 * fb + 1),
                                  BV(4 * fb + 2), BV(4 * fb + 3));
    #undef BV

    float4* row4 = reinterpret_cast<float4*>(
        attn_out + (size_t)b * T * T + (size_t)t * T);
    if (lane == 0) __stcs(&row4[fa], va);
    if (lane == 1 && fb != fa) __stcs(&row4[fb], vb);
}

// ---------------------------------------------------------------------------
extern "C" void kernel_launch(void* const* d_in, const int* in_sizes, int n_in,
                              void* d_out, int out_size)
{
    const float* x  = (const float*)d_in[0];
    const float* Wq = (const float*)d_in[1];
    const float* Wk = (const float*)d_in[2];
    const float* Wv = (const float*)d_in[3];

    float* out = (float*)d_out;
    float* op_out   = out;                     // [B*T*HS]
    float* attn_out = out + (size_t)BT * HS;   // [B*T*T]

    // Fork from the capture stream into both priority streams.
    cudaEventRecord(g_evFork, 0);
    cudaStreamWaitEvent(g_sComp, g_evFork, 0);
    cudaStreamWaitEvent(g_sZero, g_evFork, 0);

    // Grid-FIFO interleave:
    //   qkv (comp) -> z0 (zero, half) -> band (comp) -> z1 (zero, half)
    // z0's 1024 blocks backfill around qkv and cover the window until band
    // is ready; band then overlaps z1 instead of trailing the whole fill.
    dim3 g1(BT / 64, 3);
    qkv_kernel<<<g1, 256, 0, g_sComp>>>(x, Wq, Wk, Wv);

    zero_kernel<<<1024, 256, 0, g_sZero>>>(attn_out, 0);

    band_kernel<<<BT / 8, 256, 0, g_sComp>>>(op_out, attn_out);

    zero_kernel<<<1024, 256, 0, g_sZero>>>(attn_out, 8192);

    // Join both streams back into the capture stream.
    cudaEventRecord(g_evZ, g_sZero);
    cudaStreamWaitEvent(0, g_evZ, 0);
    cudaEventRecord(g_evC, g_sComp);
    cudaStreamWaitEvent(0, g_evC, 0);
}

// round 8
// speedup vs baseline: 1.0251x; 1.0251x over previous
#include <cuda_runtime.h>
#include <math.h>

// Problem constants (fixed by reference setup_inputs)
#define B  4
#define T  4096
#define C  64
#define HS 64
#define BT (B * T)

// Scratch for q, k, v projections (device globals; no allocations allowed)
__device__ float g_q[BT * HS];
__device__ float g_k[BT * HS];
__device__ float g_v[BT * HS];

// Streams with priorities + fork/join events, created once at init.
static cudaStream_t g_sZero;   // low priority  : bulk zero-fill
static cudaStream_t g_sComp;   // high priority : qkv -> band
static cudaEvent_t  g_evFork, g_evZ, g_evC;
namespace {
struct InitStreams {
    InitStreams() {
        int leastPrio = 0, greatestPrio = 0;
        cudaDeviceGetStreamPriorityRange(&leastPrio, &greatestPrio);
        cudaStreamCreateWithPriority(&g_sZero, cudaStreamNonBlocking, leastPrio);
        cudaStreamCreateWithPriority(&g_sComp, cudaStreamNonBlocking, greatestPrio);
        cudaEventCreateWithFlags(&g_evFork, cudaEventDisableTiming);
        cudaEventCreateWithFlags(&g_evZ, cudaEventDisableTiming);
        cudaEventCreateWithFlags(&g_evC, cudaEventDisableTiming);
    }
};
InitStreams g_initStreams;
}

// ---------------------------------------------------------------------------
// Kernel Z: zero-fill the attn matrix, skipping the <=2 band float4 slots per
// row (band_kernel writes those at disjoint addresses). One warp per row.
// 0 smem, 16 regs -> backfills any free warp slot alongside qkv.
// ---------------------------------------------------------------------------
__global__ __launch_bounds__(256, 8)
void zero_kernel(float* __restrict__ attn_out)   // [B, T, T]
{
    const int warp_in_blk = threadIdx.x >> 5;
    const int lane = threadIdx.x & 31;
    const int w = blockIdx.x * 8 + warp_in_blk;   // row id in [0, BT)
    const int b = w >> 12;
    const int t = w & (T - 1);

    const int lo = max(t - 2, 0);
    const int hi = min(t + 2, T - 1);
    const int fa = lo >> 2;
    const int fb = hi >> 2;

    float4* row4 = reinterpret_cast<float4*>(
        attn_out + (size_t)b * T * T + (size_t)t * T);
    const float4 z = make_float4(0.f, 0.f, 0.f, 0.f);

    #pragma unroll 4
    for (int i4 = lane; i4 < T / 4; i4 += 32) {
        if (i4 != fa && i4 != fb) __stcs(&row4[i4], z);
    }
}

// ---------------------------------------------------------------------------
// Kernel 1: QKV projection.  out[t][h] = sum_c x[t][c] * W[h][c]
// Grid: (BT/64, 3). Block: 256 threads. Tile: 64x64, 4x4 per thread.
// Smem strides padded to 68 floats (16B-aligned): inner loop = 2x LDS.128 +
// 16 FFMA per c-iter (vs 8 scalar LDS before) -> ~35% fewer issue slots.
// ---------------------------------------------------------------------------
#define QSTR 68
__global__ __launch_bounds__(256, 4)
void qkv_kernel(const float* __restrict__ x,
                const float* __restrict__ Wq,
                const float* __restrict__ Wk,
                const float* __restrict__ Wv)
{
    __shared__ float xs[64 * QSTR];   // xs[c][m] = x[row0+m][c]
    __shared__ float ws[64 * QSTR];   // ws[c][h] = W[h][c]

    const float* W;
    float* out;
    if (blockIdx.y == 0)      { W = Wq; out = g_q; }
    else if (blockIdx.y == 1) { W = Wk; out = g_k; }
    else                      { W = Wv; out = g_v; }

    const int row0 = blockIdx.x * 64;
    const int tid = threadIdx.x;

    #pragma unroll
    for (int idx = tid; idx < 64 * 64; idx += 256) {
        int h = idx >> 6, c = idx & 63;
        ws[c * QSTR + h] = W[idx];
    }
    #pragma unroll
    for (int idx = tid; idx < 64 * 64; idx += 256) {
        int m = idx >> 6, c = idx & 63;
        xs[c * QSTR + m] = x[(size_t)(row0 + m) * C + c];
    }
    __syncthreads();

    const int tm = (tid >> 4) * 4;   // 16B-aligned row group
    const int tn = (tid & 15) * 4;   // 16B-aligned col group

    float acc[4][4];
    #pragma unroll
    for (int i = 0; i < 4; i++)
        #pragma unroll
        for (int j = 0; j < 4; j++) acc[i][j] = 0.0f;

    const float4* xs4 = reinterpret_cast<const float4*>(&xs[tm]);
    const float4* ws4 = reinterpret_cast<const float4*>(&ws[tn]);

    #pragma unroll 8
    for (int c = 0; c < 64; ++c) {
        const float4 a4 = xs4[c * (QSTR / 4)];
        const float4 b4 = ws4[c * (QSTR / 4)];
        acc[0][0] += a4.x * b4.x; acc[0][1] += a4.x * b4.y;
        acc[0][2] += a4.x * b4.z; acc[0][3] += a4.x * b4.w;
        acc[1][0] += a4.y * b4.x; acc[1][1] += a4.y * b4.y;
        acc[1][2] += a4.y * b4.z; acc[1][3] += a4.y * b4.w;
        acc[2][0] += a4.z * b4.x; acc[2][1] += a4.z * b4.y;
        acc[2][2] += a4.z * b4.z; acc[2][3] += a4.z * b4.w;
        acc[3][0] += a4.w * b4.x; acc[3][1] += a4.w * b4.y;
        acc[3][2] += a4.w * b4.z; acc[3][3] += a4.w * b4.w;
    }

    #pragma unroll
    for (int i = 0; i < 4; i++) {
        float4 v4 = make_float4(acc[i][0], acc[i][1], acc[i][2], acc[i][3]);
        *reinterpret_cast<float4*>(&out[(size_t)(row0 + tm + i) * HS + tn]) = v4;
    }
}

// ---------------------------------------------------------------------------
// Kernel 2: band attention. One warp per (b, t) row: 5 dots, softmax, op row,
// and ONLY the <=2 band float4 slots of the attn row (zeros done elsewhere at
// disjoint addresses, no ordering needed).
// ---------------------------------------------------------------------------
__global__ __launch_bounds__(256, 8)
void band_kernel(float* __restrict__ op_out,    // [B*T, 64]
                 float* __restrict__ attn_out)  // [B, T, T]
{
    const int warp_in_blk = threadIdx.x >> 5;
    const int lane = threadIdx.x & 31;
    const int w = blockIdx.x * 8 + warp_in_blk;
    const int b = w >> 12;
    const int t = w & (T - 1);

    const float2 myq = reinterpret_cast<const float2*>(g_q + (size_t)w * HS)[lane];

    float score[5];
    #pragma unroll
    for (int d = 0; d < 5; ++d) {
        const int s = t - 2 + d;
        const bool valid = (unsigned)s < (unsigned)T;
        float p = 0.0f;
        if (valid) {
            const float2 kk =
                reinterpret_cast<const float2*>(g_k + ((size_t)(b * T + s)) * HS)[lane];
            p = myq.x * kk.x + myq.y * kk.y;
        }
        #pragma unroll
        for (int off = 16; off > 0; off >>= 1)
            p += __shfl_xor_sync(0xFFFFFFFFu, p, off);
        // scale = C^-0.5 = 1/8 ; triu quirk: +1.0 when s > t (d > 2)
        score[d] = valid ? (p * 0.125f + (d > 2 ? 1.0f : 0.0f)) : -1e30f;
    }

    float m = score[0];
    #pragma unroll
    for (int d = 1; d < 5; ++d) m = fmaxf(m, score[d]);
    float p5[5], sum = 0.0f;
    #pragma unroll
    for (int d = 0; d < 5; ++d) { p5[d] = expf(score[d] - m); sum += p5[d]; }
    const float inv = 1.0f / sum;
    #pragma unroll
    for (int d = 0; d < 5; ++d) p5[d] *= inv;

    // op row: each lane owns 2 channels
    float2 acc = make_float2(0.0f, 0.0f);
    #pragma unroll
    for (int d = 0; d < 5; ++d) {
        const int s = t - 2 + d;
        if ((unsigned)s < (unsigned)T) {
            const float2 vv =
                reinterpret_cast<const float2*>(g_v + ((size_t)(b * T + s)) * HS)[lane];
            acc.x += p5[d] * vv.x;
            acc.y += p5[d] * vv.y;
        }
    }
    reinterpret_cast<float2*>(op_out + (size_t)w * HS)[lane] = acc;

    // band float4 slots
    const int lo = max(t - 2, 0);
    const int hi = min(t + 2, T - 1);
    const int fa = lo >> 2;
    const int fb = hi >> 2;

    #define BV(s_) (((s_) >= lo && (s_) <= hi)                                   \
                      ? ((s_) == t - 2 ? p5[0]                                   \
                       : (s_) == t - 1 ? p5[1]                                   \
                       : (s_) == t     ? p5[2]                                   \
                       : (s_) == t + 1 ? p5[3] : p5[4])                          \
                      : 0.0f)
    const float4 va = make_float4(BV(4 * fa + 0), BV(4 * fa + 1),
                                  BV(4 * fa + 2), BV(4 * fa + 3));
    const float4 vb = make_float4(BV(4 * fb + 0), BV(4 * fb + 1),
                                  BV(4 * fb + 2), BV(4 * fb + 3));
    #undef BV

    float4* row4 = reinterpret_cast<float4*>(
        attn_out + (size_t)b * T * T + (size_t)t * T);
    if (lane == 0) __stcs(&row4[fa], va);
    if (lane == 1 && fb != fa) __stcs(&row4[fb], vb);
}

// ---------------------------------------------------------------------------
extern "C" void kernel_launch(void* const* d_in, const int* in_sizes, int n_in,
                              void* d_out, int out_size)
{
    const float* x  = (const float*)d_in[0];
    const float* Wq = (const float*)d_in[1];
    const float* Wk = (const float*)d_in[2];
    const float* Wv = (const float*)d_in[3];

    float* out = (float*)d_out;
    float* op_out   = out;                     // [B*T*HS]
    float* attn_out = out + (size_t)BT * HS;   // [B*T*T]

    // Fork from the capture stream into both priority streams.
    cudaEventRecord(g_evFork, 0);
    cudaStreamWaitEvent(g_sComp, g_evFork, 0);
    cudaStreamWaitEvent(g_sZero, g_evFork, 0);

    // Proven R6 FIFO: qkv first (smem-limited blocks placed in wave 1),
    // zero's 0-smem blocks backfill remaining warp slots immediately,
    // band backfills zero's retire-drain at the end.
    dim3 g1(BT / 64, 3);
    qkv_kernel<<<g1, 256, 0, g_sComp>>>(x, Wq, Wk, Wv);

    zero_kernel<<<BT / 8, 256, 0, g_sZero>>>(attn_out);

    band_kernel<<<BT / 8, 256, 0, g_sComp>>>(op_out, attn_out);

    // Join both streams back into the capture stream.
    cudaEventRecord(g_evZ, g_sZero);
    cudaStreamWaitEvent(0, g_evZ, 0);
    cudaEventRecord(g_evC, g_sComp);
    cudaStreamWaitEvent(0, g_evC, 0);
}